// round 6
// baseline (speedup 1.0000x reference)
#include <cuda_runtime.h>
#include <cuda_bf16.h>
#include <math.h>

#define T_SEQ 2048
#define HID   4096
#define HQ    32
#define HKV   8
#define DH    128
#define GROUPS (HQ / HKV)
#define QKV_N 6144                      // 4096 q | 1024 k | 1024 v
#define K_OFF 4096
#define V_OFF 5120

// q pre-scale: 1/sqrt(128) * log2(e)  (softmax runs in exp2 domain)
#define QSCALE_F ((float)(0.08838834764831845 * 1.4426950408889634))

// ---------------- device scratch (no allocs allowed) ----------------
__device__ float g_qkv[T_SEQ * QKV_N];      // 50 MB  fused q|k|v
__device__ float g_attn[T_SEQ * HQ * DH];   // 32 MB (tf32-rounded)
__device__ float g_Hr [T_SEQ * HID];        // 32 MB  tf32-rounded H
__device__ float g_Wr [HID * QKV_N];        // 100 MB tf32-rounded [Wq|Wk|Wv]
__device__ float g_Wor[HQ * DH * HID];      // 64 MB  tf32-rounded Wo

__device__ __forceinline__ unsigned tf32_cvt(float x) {
    unsigned r;
    asm("cvt.rna.tf32.f32 %0, %1;" : "=r"(r) : "f"(x));
    return r;
}
__device__ __forceinline__ float tf32f(float x) { return __uint_as_float(tf32_cvt(x)); }

__device__ __forceinline__ void mma_tf32(float* d, const unsigned* a, const unsigned* b) {
    asm volatile(
        "mma.sync.aligned.m16n8k8.row.col.f32.tf32.tf32.f32 "
        "{%0,%1,%2,%3}, {%4,%5,%6,%7}, {%8,%9}, {%0,%1,%2,%3};"
        : "+f"(d[0]), "+f"(d[1]), "+f"(d[2]), "+f"(d[3])
        : "r"(a[0]), "r"(a[1]), "r"(a[2]), "r"(a[3]), "r"(b[0]), "r"(b[1]));
}

__device__ __forceinline__ void cp_async16(void* smem_dst, const void* gmem_src) {
    unsigned s = (unsigned)__cvta_generic_to_shared(smem_dst);
    asm volatile("cp.async.cg.shared.global [%0], [%1], 16;" :: "r"(s), "l"(gmem_src));
}

// MUFU exp2 (force fast path)
__device__ __forceinline__ float ex2_mufu(float x) {
    float y;
    asm("ex2.approx.ftz.f32 %0, %1;" : "=f"(y) : "f"(x));
    return y;
}

// FMA-pipe exp2: minimax on f in [-0.5, 0.5], ~1e-7 rel err.
__device__ __forceinline__ float exp2_poly(float x) {
    x = fmaxf(x, -120.f);
    float t = x + 12582912.f;
    float i = t - 12582912.f;
    float f = x - i;
    float p = 1.535336188319500e-4f;
    p = fmaf(p, f, 1.339887440266574e-3f);
    p = fmaf(p, f, 9.618437357674640e-3f);
    p = fmaf(p, f, 5.550332471162809e-2f);
    p = fmaf(p, f, 2.402264791363012e-1f);
    p = fmaf(p, f, 6.931472028550421e-1f);
    p = fmaf(p, f, 1.0f);
    int ii = (int)i;
    return p * __int_as_float((ii + 127) << 23);
}

// ---------------------------------------------------------------------------
// Pre-round fp32 -> tf32
// ---------------------------------------------------------------------------
__global__ void round_tf32_kernel(const float4* __restrict__ src,
                                  float4* __restrict__ dst, int n4)
{
    int i = blockIdx.x * blockDim.x + threadIdx.x;
    int stride = gridDim.x * blockDim.x;
    for (; i < n4; i += stride) {
        float4 v = src[i];
        v.x = tf32f(v.x); v.y = tf32f(v.y); v.z = tf32f(v.z); v.w = tf32f(v.w);
        dst[i] = v;
    }
}

__global__ void round_tf32_strided(const float4* __restrict__ src,
                                   float4* __restrict__ dst, int n4,
                                   int srcW4, int dstW4, int colOff4)
{
    int i = blockIdx.x * blockDim.x + threadIdx.x;
    int stride = gridDim.x * blockDim.x;
    for (; i < n4; i += stride) {
        int r = i / srcW4, c = i - r * srcW4;
        float4 v = src[i];
        v.x = tf32f(v.x); v.y = tf32f(v.y); v.z = tf32f(v.z); v.w = tf32f(v.w);
        dst[(size_t)r * dstW4 + colOff4 + c] = v;
    }
}

// ---------------------------------------------------------------------------
// TF32 tensor GEMM, 3-stage cp.async pipeline. C[M,N] = A[M,K] @ B[K,N].
// Tile 128x128x32, 8 warps, warp 64x32. Single __syncthreads per K-iter.
// Stage s: As = sm + s*8960 ([128][36]); Bs = sm + s*8960 + 4608 ([32][136]).
// ---------------------------------------------------------------------------
#define GEMM_SMEM_BYTES (3 * (128 * 36 + 32 * 136) * 4)

__global__ __launch_bounds__(256, 2) void tf32gemm3(const float* __restrict__ A,
                                                    const float* __restrict__ B,
                                                    float* __restrict__ C,
                                                    int M, int N, int K)
{
    extern __shared__ float sm[];
    const int tid  = threadIdx.x;
    const int wid  = tid >> 5;
    const int lane = tid & 31;
    const int g    = lane >> 2;
    const int tg   = lane & 3;
    const int wm   = (wid >> 2) * 64;
    const int wn   = (wid & 3) * 32;
    const int bm   = blockIdx.y * 128;
    const int bn   = blockIdx.x * 128;

    const float* Ab = A + (size_t)bm * K;
    const float* Bb = B + bn;

    float acc[4][4][4];
#pragma unroll
    for (int mt = 0; mt < 4; mt++)
#pragma unroll
        for (int nt = 0; nt < 4; nt++)
#pragma unroll
            for (int i = 0; i < 4; i++) acc[mt][nt][i] = 0.f;

    const int ntiles = K >> 5;

    auto issue = [&](int t) {
        float* As_ = sm + (t % 3) * 8960;
        float* Bs_ = As_ + 4608;
        const int kt = t << 5;
#pragma unroll
        for (int i_ = 0; i_ < 4; i_++) {
            int f4 = tid + i_ * 256;
            int r_ = f4 >> 3, c4_ = (f4 & 7) << 2;
            cp_async16(As_ + r_ * 36 + c4_, Ab + (size_t)r_ * K + kt + c4_);
            int rb_ = f4 >> 5, cb4_ = (f4 & 31) << 2;
            cp_async16(Bs_ + rb_ * 136 + cb4_, Bb + (size_t)(kt + rb_) * N + cb4_);
        }
        asm volatile("cp.async.commit_group;");
    };

    issue(0);
    issue(1);

    for (int t = 0; t < ntiles; t++) {
        if (t == ntiles - 1) asm volatile("cp.async.wait_group 0;");
        else                 asm volatile("cp.async.wait_group 1;");
        __syncthreads();               // stage t visible; compute(t-1) done by all
        if (t + 2 < ntiles) issue(t + 2);   // overwrites stage (t-1)%3 — safe

        const float* As_ = sm + (t % 3) * 8960;
        const float* Bs_ = As_ + 4608;
#pragma unroll
        for (int kk = 0; kk < 32; kk += 8) {
            unsigned af[4][4], bf[4][2];
#pragma unroll
            for (int mt = 0; mt < 4; mt++) {
                int row = wm + mt * 16;
                af[mt][0] = __float_as_uint(As_[(row + g) * 36 + kk + tg]);
                af[mt][1] = __float_as_uint(As_[(row + g + 8) * 36 + kk + tg]);
                af[mt][2] = __float_as_uint(As_[(row + g) * 36 + kk + tg + 4]);
                af[mt][3] = __float_as_uint(As_[(row + g + 8) * 36 + kk + tg + 4]);
            }
#pragma unroll
            for (int nt = 0; nt < 4; nt++) {
                int col = wn + nt * 8;
                bf[nt][0] = __float_as_uint(Bs_[(kk + tg) * 136 + col + g]);
                bf[nt][1] = __float_as_uint(Bs_[(kk + tg + 4) * 136 + col + g]);
            }
#pragma unroll
            for (int mt = 0; mt < 4; mt++)
#pragma unroll
                for (int nt = 0; nt < 4; nt++)
                    mma_tf32(acc[mt][nt], af[mt], bf[nt]);
        }
    }

#pragma unroll
    for (int mt = 0; mt < 4; mt++) {
#pragma unroll
        for (int nt = 0; nt < 4; nt++) {
            int row = bm + wm + mt * 16 + g;
            int col = bn + wn + nt * 8 + tg * 2;
            *(float2*)&C[(size_t)row * N + col]       = make_float2(acc[mt][nt][0], acc[mt][nt][1]);
            *(float2*)&C[(size_t)(row + 8) * N + col] = make_float2(acc[mt][nt][2], acc[mt][nt][3]);
        }
    }
}

// ---------------------------------------------------------------------------
// RoPE in-place on fused qkv. Q pre-scaled by 1/sqrt(D)*log2(e). tf32 rounding.
// ---------------------------------------------------------------------------
__global__ void rope_round_kernel(const float* __restrict__ cosp,
                                  const float* __restrict__ sinp)
{
    const int t = blockIdx.x;
    float* rowp = &g_qkv[(size_t)t * QKV_N];
    for (int p = threadIdx.x; p < (HQ + HKV) * 64; p += blockDim.x) {
        int h = p >> 6;
        int d = p & 63;
        float c = cosp[t * DH + d];
        float s = sinp[t * DH + d];
        float* base = (h < HQ) ? rowp + h * DH : rowp + K_OFF + (h - HQ) * DH;
        float sc = (h < HQ) ? QSCALE_F : 1.0f;
        float x1 = base[d];
        float x2 = base[d + 64];
        base[d]      = tf32f((x1 * c - x2 * s) * sc);
        base[d + 64] = tf32f((x2 * c + x1 * s) * sc);
    }
    for (int i = threadIdx.x; i < HKV * DH; i += blockDim.x) {
        float* pv = rowp + V_OFF + i;
        *pv = tf32f(*pv);
    }
}

// ---------------------------------------------------------------------------
// Flash attention v2: 4 GQA heads per CTA, 512 threads (16 warps).
// K/V loaded once per KV-head group, cp.async double-buffered.
// Warp (wid): head_local = wid>>2, 16 query rows = (wid&3)*16.
// smem floats: K0[64*132] V0[64*136] K1[64*132] V1[64*136] Ps[4][64*68]
//   offsets:   0          8448       17152      25600      34304
// Q tiles staged through K0..V1 region (4 x 64*132) before the main loop.
// ---------------------------------------------------------------------------
#define ATT_SMEM_BYTES ((34304 + 4 * 64 * 68) * 4)   // 206,848 B

__global__ __launch_bounds__(512, 1) void attn_mma_kernel()
{
    extern __shared__ float smf[];
    float* Kbuf[2] = { smf,         smf + 17152 };
    float* Vbuf[2] = { smf + 8448,  smf + 25600 };
    const int tid  = threadIdx.x;
    const int wid  = tid >> 5;
    const int lane = tid & 31;
    const int g    = lane >> 2;
    const int tg   = lane & 3;
    const int hl   = wid >> 2;          // head within group 0..3
    const int wrow = (wid & 3) * 16;    // query-row block within head tile
    const int kvh  = blockIdx.y;
    const int h    = kvh * GROUPS + hl;
    const int qi   = gridDim.x - 1 - blockIdx.x;   // long CTAs first
    const int q0   = qi * 64;
    float* Psh = smf + 34304 + hl * (64 * 68);

    // ---- stage all 4 heads' Q tiles into the K/V buffer region
    for (int i = 0; i < 16; i++) {
        int idx = tid + i * 512;            // 0..8191
        int hh  = idx >> 11;                // head 0..3 (2048 float4 each)
        int rem = idx & 2047;
        int r = rem >> 5, c4 = (rem & 31) << 2;
        *(float4*)&smf[hh * 8448 + r * 132 + c4] =
            *(const float4*)&g_qkv[(size_t)(q0 + r) * QKV_N + (kvh * GROUPS + hh) * DH + c4];
    }
    __syncthreads();

    unsigned qf[16][4];
    {
        const float* Qs = smf + hl * 8448;
#pragma unroll
        for (int kk8 = 0; kk8 < 16; kk8++) {
            qf[kk8][0] = __float_as_uint(Qs[(wrow + g) * 132 + kk8 * 8 + tg]);
            qf[kk8][1] = __float_as_uint(Qs[(wrow + g + 8) * 132 + kk8 * 8 + tg]);
            qf[kk8][2] = __float_as_uint(Qs[(wrow + g) * 132 + kk8 * 8 + tg + 4]);
            qf[kk8][3] = __float_as_uint(Qs[(wrow + g + 8) * 132 + kk8 * 8 + tg + 4]);
        }
    }
    __syncthreads();   // all frags read before K/V loads overwrite region

    const int ntiles = qi + 1;

    auto issue = [&](int t) {
        float* Kd = Kbuf[t & 1];
        float* Vd = Vbuf[t & 1];
        const int k0 = t * 64;
#pragma unroll
        for (int i = 0; i < 8; i++) {
            int idx = tid + i * 512;        // 0..4095
            int isv = idx >> 11;            // 0 = K, 1 = V
            int rem = idx & 2047;
            int r = rem >> 5, c4 = (rem & 31) << 2;
            size_t go = (size_t)(k0 + r) * QKV_N + kvh * DH + c4;
            if (isv) cp_async16(Vd + r * 136 + c4, &g_qkv[go + V_OFF]);
            else     cp_async16(Kd + r * 132 + c4, &g_qkv[go + K_OFF]);
        }
        asm volatile("cp.async.commit_group;");
    };

    float acc_o[16][4];
#pragma unroll
    for (int nt = 0; nt < 16; nt++)
#pragma unroll
        for (int i = 0; i < 4; i++) acc_o[nt][i] = 0.f;
    float l0 = 0.f, l1 = 0.f;

    issue(0);

    for (int t = 0; t < ntiles; t++) {
        if (t + 1 < ntiles) {
            issue(t + 1);                               // buf (t+1)&1: freed by end-of-iter sync(t-1)
            asm volatile("cp.async.wait_group 1;");     // tile t complete
        } else {
            asm volatile("cp.async.wait_group 0;");
        }
        __syncthreads();

        const float* Ks = Kbuf[t & 1];
        const float* Vs = Vbuf[t & 1];
        const int k0 = t * 64;

        // ---- S2 = Qscaled @ K^T (log2-domain)
        float acc_s[8][4];
#pragma unroll
        for (int nt = 0; nt < 8; nt++)
#pragma unroll
            for (int i = 0; i < 4; i++) acc_s[nt][i] = 0.f;
#pragma unroll
        for (int kk8 = 0; kk8 < 16; kk8++) {
#pragma unroll
            for (int nt = 0; nt < 8; nt++) {
                unsigned b[2];
                b[0] = __float_as_uint(Ks[(nt * 8 + g) * 132 + kk8 * 8 + tg]);
                b[1] = __float_as_uint(Ks[(nt * 8 + g) * 132 + kk8 * 8 + tg + 4]);
                mma_tf32(acc_s[nt], qf[kk8], b);
            }
        }

        // ---- p = 2^(s2 - 32); causal mask on diagonal tile; no max tracking
        const bool diag = (t == ntiles - 1);
        const int r0 = q0 + wrow + g, r1 = r0 + 8;
#pragma unroll
        for (int nt = 0; nt < 8; nt++) {
            float x0 = acc_s[nt][0] - 32.f;
            float x1 = acc_s[nt][1] - 32.f;
            float x2 = acc_s[nt][2] - 32.f;
            float x3 = acc_s[nt][3] - 32.f;
            if (diag) {
                int col0 = k0 + nt * 8 + tg * 2;
                if (col0     > r0) x0 = -1e30f;
                if (col0 + 1 > r0) x1 = -1e30f;
                if (col0     > r1) x2 = -1e30f;
                if (col0 + 1 > r1) x3 = -1e30f;
            }
            float p0, p1, p2, p3;
            if (nt < 3) {                  // 37.5% on FMA pipe
                p0 = exp2_poly(x0); p1 = exp2_poly(x1);
                p2 = exp2_poly(x2); p3 = exp2_poly(x3);
            } else {                       // 62.5% on MUFU
                p0 = ex2_mufu(x0); p1 = ex2_mufu(x1);
                p2 = ex2_mufu(x2); p3 = ex2_mufu(x3);
            }
            l0 += p0 + p1;
            l1 += p2 + p3;
            *(float2*)&Psh[(wrow + g) * 68 + nt * 8 + tg * 2]     = make_float2(tf32f(p0), tf32f(p1));
            *(float2*)&Psh[(wrow + g + 8) * 68 + nt * 8 + tg * 2] = make_float2(tf32f(p2), tf32f(p3));
        }
        __syncwarp();   // Ps rows are warp-private

        // ---- O += P @ V
#pragma unroll
        for (int kk8 = 0; kk8 < 8; kk8++) {
            unsigned a[4];
            a[0] = __float_as_uint(Psh[(wrow + g) * 68 + kk8 * 8 + tg]);
            a[1] = __float_as_uint(Psh[(wrow + g + 8) * 68 + kk8 * 8 + tg]);
            a[2] = __float_as_uint(Psh[(wrow + g) * 68 + kk8 * 8 + tg + 4]);
            a[3] = __float_as_uint(Psh[(wrow + g + 8) * 68 + kk8 * 8 + tg + 4]);
#pragma unroll
            for (int nt = 0; nt < 16; nt++) {
                unsigned b[2];
                b[0] = __float_as_uint(Vs[(kk8 * 8 + tg) * 136 + nt * 8 + g]);
                b[1] = __float_as_uint(Vs[(kk8 * 8 + tg + 4) * 136 + nt * 8 + g]);
                mma_tf32(acc_o[nt], a, b);
            }
        }
        __syncthreads();   // all warps done reading buf t before issue(t+2) reuses it
    }

    // ---- denominator reduce once per row
    l0 += __shfl_xor_sync(0xffffffffu, l0, 1);
    l0 += __shfl_xor_sync(0xffffffffu, l0, 2);
    l1 += __shfl_xor_sync(0xffffffffu, l1, 1);
    l1 += __shfl_xor_sync(0xffffffffu, l1, 2);
    const float inv0 = 1.f / l0;
    const float inv1 = 1.f / l1;

    const int row0 = q0 + wrow + g, row1 = row0 + 8;
#pragma unroll
    for (int nt = 0; nt < 16; nt++) {
        int col = h * DH + nt * 8 + tg * 2;
        *(float2*)&g_attn[(size_t)row0 * (HQ * DH) + col] =
            make_float2(tf32f(acc_o[nt][0] * inv0), tf32f(acc_o[nt][1] * inv0));
        *(float2*)&g_attn[(size_t)row1 * (HQ * DH) + col] =
            make_float2(tf32f(acc_o[nt][2] * inv1), tf32f(acc_o[nt][3] * inv1));
    }
}

// ---------------------------------------------------------------------------
// Launch pipeline. Inputs (metadata order):
// 0: hidden_states [2048,4096] f32   1: position_ids (unused)
// 2: cos [2048,128] f32              3: sin [2048,128] f32
// 4: Wq [4096,4096]  5: Wk [4096,1024]  6: Wv [4096,1024]  7: Wo [4096,4096]
// out: [2048,4096] f32
// ---------------------------------------------------------------------------
extern "C" void kernel_launch(void* const* d_in, const int* in_sizes, int n_in,
                              void* d_out, int out_size)
{
    const float* H    = (const float*)d_in[0];
    const float* cosp = (const float*)d_in[2];
    const float* sinp = (const float*)d_in[3];
    const float* Wq   = (const float*)d_in[4];
    const float* Wk   = (const float*)d_in[5];
    const float* Wv   = (const float*)d_in[6];
    const float* Wo   = (const float*)d_in[7];
    float* out = (float*)d_out;

    float *qkv, *attn, *Hr, *Wr, *Wor;
    cudaGetSymbolAddress((void**)&qkv,  g_qkv);
    cudaGetSymbolAddress((void**)&attn, g_attn);
    cudaGetSymbolAddress((void**)&Hr,   g_Hr);
    cudaGetSymbolAddress((void**)&Wr,   g_Wr);
    cudaGetSymbolAddress((void**)&Wor,  g_Wor);

    cudaFuncSetAttribute(tf32gemm3, cudaFuncAttributeMaxDynamicSharedMemorySize, GEMM_SMEM_BYTES);
    cudaFuncSetAttribute(attn_mma_kernel, cudaFuncAttributeMaxDynamicSharedMemorySize, ATT_SMEM_BYTES);

    // Prep: round H / Wo, pack Wq|Wk|Wv rounded into fused [4096][6144]
    round_tf32_kernel<<<512, 256>>>((const float4*)H,  (float4*)Hr,  T_SEQ * HID / 4);
    round_tf32_kernel<<<1024, 256>>>((const float4*)Wo, (float4*)Wor, HQ * DH * HID / 4);
    round_tf32_strided<<<1024, 256>>>((const float4*)Wq, (float4*)Wr, HID * 4096 / 4,
                                      1024, QKV_N / 4, 0);
    round_tf32_strided<<<512, 256>>>((const float4*)Wk, (float4*)Wr, HID * 1024 / 4,
                                     256, QKV_N / 4, 1024);
    round_tf32_strided<<<512, 256>>>((const float4*)Wv, (float4*)Wr, HID * 1024 / 4,
                                     256, QKV_N / 4, 1280);

    // Fused QKV projection (one GEMM, N=6144)
    tf32gemm3<<<dim3(QKV_N / 128, T_SEQ / 128), 256, GEMM_SMEM_BYTES>>>(
        Hr, Wr, qkv, T_SEQ, QKV_N, HID);

    // RoPE + q prescale + tf32 rounding
    rope_round_kernel<<<T_SEQ, 256>>>(cosp, sinp);

    // Causal GQA attention: 4 heads/CTA, double-buffered
    attn_mma_kernel<<<dim3(T_SEQ / 64, HKV), 512, ATT_SMEM_BYTES>>>();

    // Output projection
    tf32gemm3<<<dim3(HID / 128, T_SEQ / 128), 256, GEMM_SMEM_BYTES>>>(
        attn, Wor, out, T_SEQ, HID, HQ * DH);
}

// round 7
// speedup vs baseline: 1.1778x; 1.1778x over previous
#include <cuda_runtime.h>
#include <cuda_bf16.h>
#include <math.h>

#define T_SEQ 2048
#define HID   4096
#define HQ    32
#define HKV   8
#define DH    128
#define GROUPS (HQ / HKV)
#define QKV_N 6144                      // 4096 q | 1024 k | 1024 v
#define K_OFF 4096
#define V_OFF 5120

// q pre-scale: 1/sqrt(128) * log2(e)  (softmax runs in exp2 domain)
#define QSCALE_F ((float)(0.08838834764831845 * 1.4426950408889634))

// ---------------- device scratch (no allocs allowed) ----------------
__device__ float g_qkv[T_SEQ * QKV_N];      // 50 MB  fused q|k|v
__device__ float g_attn[T_SEQ * HQ * DH];   // 32 MB (tf32-rounded)
__device__ float g_Hr [T_SEQ * HID];        // 32 MB  tf32-rounded H
__device__ float g_Wr [HID * QKV_N];        // 100 MB tf32-rounded [Wq|Wk|Wv]
__device__ float g_Wor[HQ * DH * HID];      // 64 MB  tf32-rounded Wo

__device__ __forceinline__ unsigned tf32_cvt(float x) {
    unsigned r;
    asm("cvt.rna.tf32.f32 %0, %1;" : "=r"(r) : "f"(x));
    return r;
}
__device__ __forceinline__ float tf32f(float x) { return __uint_as_float(tf32_cvt(x)); }

__device__ __forceinline__ void mma_tf32(float* d, const unsigned* a, const unsigned* b) {
    asm volatile(
        "mma.sync.aligned.m16n8k8.row.col.f32.tf32.tf32.f32 "
        "{%0,%1,%2,%3}, {%4,%5,%6,%7}, {%8,%9}, {%0,%1,%2,%3};"
        : "+f"(d[0]), "+f"(d[1]), "+f"(d[2]), "+f"(d[3])
        : "r"(a[0]), "r"(a[1]), "r"(a[2]), "r"(a[3]), "r"(b[0]), "r"(b[1]));
}

__device__ __forceinline__ void cp_async16(void* smem_dst, const void* gmem_src) {
    unsigned s = (unsigned)__cvta_generic_to_shared(smem_dst);
    asm volatile("cp.async.cg.shared.global [%0], [%1], 16;" :: "r"(s), "l"(gmem_src));
}

// MUFU exp2 (force fast path)
__device__ __forceinline__ float ex2_mufu(float x) {
    float y;
    asm("ex2.approx.ftz.f32 %0, %1;" : "=f"(y) : "f"(x));
    return y;
}

// FMA-pipe exp2: minimax on f in [-0.5, 0.5], ~1e-7 rel err.
__device__ __forceinline__ float exp2_poly(float x) {
    x = fmaxf(x, -120.f);
    float t = x + 12582912.f;
    float i = t - 12582912.f;
    float f = x - i;
    float p = 1.535336188319500e-4f;
    p = fmaf(p, f, 1.339887440266574e-3f);
    p = fmaf(p, f, 9.618437357674640e-3f);
    p = fmaf(p, f, 5.550332471162809e-2f);
    p = fmaf(p, f, 2.402264791363012e-1f);
    p = fmaf(p, f, 6.931472028550421e-1f);
    p = fmaf(p, f, 1.0f);
    int ii = (int)i;
    return p * __int_as_float((ii + 127) << 23);
}

// ---------------------------------------------------------------------------
// Prep 1: round H and Wo to tf32 (two regions, one launch)
// ---------------------------------------------------------------------------
__global__ void prep_round_HWo(const float4* __restrict__ H, float4* __restrict__ Hr,
                               const float4* __restrict__ Wo, float4* __restrict__ Wor)
{
    const int nH = T_SEQ * HID / 4;
    const int nO = HQ * DH * HID / 4;
    int stride = gridDim.x * blockDim.x;
    for (int i = blockIdx.x * blockDim.x + threadIdx.x; i < nH + nO; i += stride) {
        const float4* s = (i < nH) ? H + i : Wo + (i - nH);
        float4* d       = (i < nH) ? Hr + i : Wor + (i - nH);
        float4 v = *s;
        v.x = tf32f(v.x); v.y = tf32f(v.y); v.z = tf32f(v.z); v.w = tf32f(v.w);
        *d = v;
    }
}

// Prep 2: pack Wq (rounded) into fused weight at col offset 0
__global__ void prep_pack_Wq(const float4* __restrict__ Wq, float4* __restrict__ Wr)
{
    const int n4 = HID * 4096 / 4;
    int stride = gridDim.x * blockDim.x;
    for (int i = blockIdx.x * blockDim.x + threadIdx.x; i < n4; i += stride) {
        int r = i >> 10, c = i & 1023;            // srcW4 = 1024
        float4 v = Wq[i];
        v.x = tf32f(v.x); v.y = tf32f(v.y); v.z = tf32f(v.z); v.w = tf32f(v.w);
        Wr[(size_t)r * (QKV_N / 4) + c] = v;
    }
}

// Prep 3: pack Wk (col 1024) and Wv (col 1280)
__global__ void prep_pack_WkWv(const float4* __restrict__ Wk,
                               const float4* __restrict__ Wv, float4* __restrict__ Wr)
{
    const int n4 = HID * 1024 / 4;                // per matrix
    int stride = gridDim.x * blockDim.x;
    for (int i = blockIdx.x * blockDim.x + threadIdx.x; i < 2 * n4; i += stride) {
        int which = (i >= n4);
        int j = which ? i - n4 : i;
        int r = j >> 8, c = j & 255;              // srcW4 = 256
        float4 v = which ? Wv[j] : Wk[j];
        v.x = tf32f(v.x); v.y = tf32f(v.y); v.z = tf32f(v.z); v.w = tf32f(v.w);
        Wr[(size_t)r * (QKV_N / 4) + (which ? 1280 : 1024) + c] = v;
    }
}

// ---------------------------------------------------------------------------
// TF32 tensor GEMM, 3-stage cp.async pipeline. C[M,N] = A[M,K] @ B[K,N].
// Tile 128x128x32, 8 warps, warp 64x32. Single __syncthreads per K-iter.
// ---------------------------------------------------------------------------
#define GEMM_SMEM_BYTES (3 * (128 * 36 + 32 * 136) * 4)

__global__ __launch_bounds__(256, 2) void tf32gemm3(const float* __restrict__ A,
                                                    const float* __restrict__ B,
                                                    float* __restrict__ C,
                                                    int M, int N, int K)
{
    extern __shared__ float sm[];
    const int tid  = threadIdx.x;
    const int wid  = tid >> 5;
    const int lane = tid & 31;
    const int g    = lane >> 2;
    const int tg   = lane & 3;
    const int wm   = (wid >> 2) * 64;
    const int wn   = (wid & 3) * 32;
    const int bm   = blockIdx.y * 128;
    const int bn   = blockIdx.x * 128;

    const float* Ab = A + (size_t)bm * K;
    const float* Bb = B + bn;

    float acc[4][4][4];
#pragma unroll
    for (int mt = 0; mt < 4; mt++)
#pragma unroll
        for (int nt = 0; nt < 4; nt++)
#pragma unroll
            for (int i = 0; i < 4; i++) acc[mt][nt][i] = 0.f;

    const int ntiles = K >> 5;

    auto issue = [&](int t) {
        float* As_ = sm + (t % 3) * 8960;
        float* Bs_ = As_ + 4608;
        const int kt = t << 5;
#pragma unroll
        for (int i_ = 0; i_ < 4; i_++) {
            int f4 = tid + i_ * 256;
            int r_ = f4 >> 3, c4_ = (f4 & 7) << 2;
            cp_async16(As_ + r_ * 36 + c4_, Ab + (size_t)r_ * K + kt + c4_);
            int rb_ = f4 >> 5, cb4_ = (f4 & 31) << 2;
            cp_async16(Bs_ + rb_ * 136 + cb4_, Bb + (size_t)(kt + rb_) * N + cb4_);
        }
        asm volatile("cp.async.commit_group;");
    };

    issue(0);
    issue(1);

    for (int t = 0; t < ntiles; t++) {
        if (t == ntiles - 1) asm volatile("cp.async.wait_group 0;");
        else                 asm volatile("cp.async.wait_group 1;");
        __syncthreads();
        if (t + 2 < ntiles) issue(t + 2);

        const float* As_ = sm + (t % 3) * 8960;
        const float* Bs_ = As_ + 4608;
#pragma unroll
        for (int kk = 0; kk < 32; kk += 8) {
            unsigned af[4][4], bf[4][2];
#pragma unroll
            for (int mt = 0; mt < 4; mt++) {
                int row = wm + mt * 16;
                af[mt][0] = __float_as_uint(As_[(row + g) * 36 + kk + tg]);
                af[mt][1] = __float_as_uint(As_[(row + g + 8) * 36 + kk + tg]);
                af[mt][2] = __float_as_uint(As_[(row + g) * 36 + kk + tg + 4]);
                af[mt][3] = __float_as_uint(As_[(row + g + 8) * 36 + kk + tg + 4]);
            }
#pragma unroll
            for (int nt = 0; nt < 4; nt++) {
                int col = wn + nt * 8;
                bf[nt][0] = __float_as_uint(Bs_[(kk + tg) * 136 + col + g]);
                bf[nt][1] = __float_as_uint(Bs_[(kk + tg + 4) * 136 + col + g]);
            }
#pragma unroll
            for (int mt = 0; mt < 4; mt++)
#pragma unroll
                for (int nt = 0; nt < 4; nt++)
                    mma_tf32(acc[mt][nt], af[mt], bf[nt]);
        }
    }

#pragma unroll
    for (int mt = 0; mt < 4; mt++) {
#pragma unroll
        for (int nt = 0; nt < 4; nt++) {
            int row = bm + wm + mt * 16 + g;
            int col = bn + wn + nt * 8 + tg * 2;
            *(float2*)&C[(size_t)row * N + col]       = make_float2(acc[mt][nt][0], acc[mt][nt][1]);
            *(float2*)&C[(size_t)(row + 8) * N + col] = make_float2(acc[mt][nt][2], acc[mt][nt][3]);
        }
    }
}

// ---------------------------------------------------------------------------
// RoPE in-place on fused qkv. Q pre-scaled by 1/sqrt(D)*log2(e). tf32 rounding.
// ---------------------------------------------------------------------------
__global__ void rope_round_kernel(const float* __restrict__ cosp,
                                  const float* __restrict__ sinp)
{
    const int t = blockIdx.x;
    float* rowp = &g_qkv[(size_t)t * QKV_N];
    for (int p = threadIdx.x; p < (HQ + HKV) * 64; p += blockDim.x) {
        int h = p >> 6;
        int d = p & 63;
        float c = cosp[t * DH + d];
        float s = sinp[t * DH + d];
        float* base = (h < HQ) ? rowp + h * DH : rowp + K_OFF + (h - HQ) * DH;
        float sc = (h < HQ) ? QSCALE_F : 1.0f;
        float x1 = base[d];
        float x2 = base[d + 64];
        base[d]      = tf32f((x1 * c - x2 * s) * sc);
        base[d + 64] = tf32f((x2 * c + x1 * s) * sc);
    }
    for (int i = threadIdx.x; i < HKV * DH; i += blockDim.x) {
        float* pv = rowp + V_OFF + i;
        *pv = tf32f(*pv);
    }
}

// ---------------------------------------------------------------------------
// Tensor-core flash attention (R5 config: 64 queries x 1 head, 128 threads,
// 2 CTAs/SM). No-max exp2 softmax; 25% poly / 75% MUFU exp split.
// smem: Ks[64][132] Vs[64][136] Ps[64][68]
// ---------------------------------------------------------------------------
#define ATT_SMEM_BYTES ((64 * 132 + 64 * 136 + 64 * 68) * 4)

__global__ __launch_bounds__(128, 2) void attn_mma_kernel()
{
    extern __shared__ float smf[];
    float* Ks = smf;                 // [64][132]
    float* Vs = smf + 64 * 132;      // [64][136]
    float* Ps = Vs + 64 * 136;       // [64][68]

    const int h    = blockIdx.y;
    const int kvh  = h / GROUPS;
    const int qi   = gridDim.x - 1 - blockIdx.x;   // long CTAs first
    const int q0   = qi * 64;
    const int tid  = threadIdx.x;
    const int w    = tid >> 5;
    const int lane = tid & 31;
    const int g    = lane >> 2;
    const int tg   = lane & 3;
    const int wrow = w * 16;

    for (int idx = tid; idx < 64 * 32; idx += 128) {
        int r = idx >> 5, c4 = (idx & 31) << 2;
        *(float4*)&Ks[r * 132 + c4] =
            *(const float4*)&g_qkv[(size_t)(q0 + r) * QKV_N + h * DH + c4];
    }
    __syncthreads();
    unsigned qf[16][4];
#pragma unroll
    for (int kk8 = 0; kk8 < 16; kk8++) {
        qf[kk8][0] = __float_as_uint(Ks[(wrow + g) * 132 + kk8 * 8 + tg]);
        qf[kk8][1] = __float_as_uint(Ks[(wrow + g + 8) * 132 + kk8 * 8 + tg]);
        qf[kk8][2] = __float_as_uint(Ks[(wrow + g) * 132 + kk8 * 8 + tg + 4]);
        qf[kk8][3] = __float_as_uint(Ks[(wrow + g + 8) * 132 + kk8 * 8 + tg + 4]);
    }
    __syncthreads();

    float acc_o[16][4];
#pragma unroll
    for (int nt = 0; nt < 16; nt++)
#pragma unroll
        for (int i = 0; i < 4; i++) acc_o[nt][i] = 0.f;
    float l0 = 0.f, l1 = 0.f;

    for (int k0 = 0; k0 <= q0; k0 += 64) {
        for (int idx = tid; idx < 64 * 32; idx += 128) {
            int r = idx >> 5, c4 = (idx & 31) << 2;
            size_t off = (size_t)(k0 + r) * QKV_N + kvh * DH + c4;
            *(float4*)&Ks[r * 132 + c4] = *(const float4*)&g_qkv[off + K_OFF];
            *(float4*)&Vs[r * 136 + c4] = *(const float4*)&g_qkv[off + V_OFF];
        }
        __syncthreads();

        float acc_s[8][4];
#pragma unroll
        for (int nt = 0; nt < 8; nt++)
#pragma unroll
            for (int i = 0; i < 4; i++) acc_s[nt][i] = 0.f;
#pragma unroll
        for (int kk8 = 0; kk8 < 16; kk8++) {
#pragma unroll
            for (int nt = 0; nt < 8; nt++) {
                unsigned b[2];
                b[0] = __float_as_uint(Ks[(nt * 8 + g) * 132 + kk8 * 8 + tg]);
                b[1] = __float_as_uint(Ks[(nt * 8 + g) * 132 + kk8 * 8 + tg + 4]);
                mma_tf32(acc_s[nt], qf[kk8], b);
            }
        }

        const bool diag = (k0 == q0);
        const int r0 = q0 + wrow + g, r1 = r0 + 8;
#pragma unroll
        for (int nt = 0; nt < 8; nt++) {
            float x0 = acc_s[nt][0] - 32.f;
            float x1 = acc_s[nt][1] - 32.f;
            float x2 = acc_s[nt][2] - 32.f;
            float x3 = acc_s[nt][3] - 32.f;
            if (diag) {
                int col0 = k0 + nt * 8 + tg * 2;
                if (col0     > r0) x0 = -1e30f;
                if (col0 + 1 > r0) x1 = -1e30f;
                if (col0     > r1) x2 = -1e30f;
                if (col0 + 1 > r1) x3 = -1e30f;
            }
            float p0, p1, p2, p3;
            if (nt < 2) {                      // 25% on FMA pipe
                p0 = exp2_poly(x0); p1 = exp2_poly(x1);
                p2 = exp2_poly(x2); p3 = exp2_poly(x3);
            } else {                           // 75% on MUFU
                p0 = ex2_mufu(x0); p1 = ex2_mufu(x1);
                p2 = ex2_mufu(x2); p3 = ex2_mufu(x3);
            }
            l0 += p0 + p1;
            l1 += p2 + p3;
            *(float2*)&Ps[(wrow + g) * 68 + nt * 8 + tg * 2]     = make_float2(tf32f(p0), tf32f(p1));
            *(float2*)&Ps[(wrow + g + 8) * 68 + nt * 8 + tg * 2] = make_float2(tf32f(p2), tf32f(p3));
        }
        __syncwarp();

#pragma unroll
        for (int kk8 = 0; kk8 < 8; kk8++) {
            unsigned a[4];
            a[0] = __float_as_uint(Ps[(wrow + g) * 68 + kk8 * 8 + tg]);
            a[1] = __float_as_uint(Ps[(wrow + g + 8) * 68 + kk8 * 8 + tg]);
            a[2] = __float_as_uint(Ps[(wrow + g) * 68 + kk8 * 8 + tg + 4]);
            a[3] = __float_as_uint(Ps[(wrow + g + 8) * 68 + kk8 * 8 + tg + 4]);
#pragma unroll
            for (int nt = 0; nt < 16; nt++) {
                unsigned b[2];
                b[0] = __float_as_uint(Vs[(kk8 * 8 + tg) * 136 + nt * 8 + g]);
                b[1] = __float_as_uint(Vs[(kk8 * 8 + tg + 4) * 136 + nt * 8 + g]);
                mma_tf32(acc_o[nt], a, b);
            }
        }
        __syncthreads();
    }

    l0 += __shfl_xor_sync(0xffffffffu, l0, 1);
    l0 += __shfl_xor_sync(0xffffffffu, l0, 2);
    l1 += __shfl_xor_sync(0xffffffffu, l1, 1);
    l1 += __shfl_xor_sync(0xffffffffu, l1, 2);
    const float inv0 = 1.f / l0;
    const float inv1 = 1.f / l1;

    const int row0 = q0 + wrow + g, row1 = row0 + 8;
#pragma unroll
    for (int nt = 0; nt < 16; nt++) {
        int col = h * DH + nt * 8 + tg * 2;
        *(float2*)&g_attn[(size_t)row0 * (HQ * DH) + col] =
            make_float2(tf32f(acc_o[nt][0] * inv0), tf32f(acc_o[nt][1] * inv0));
        *(float2*)&g_attn[(size_t)row1 * (HQ * DH) + col] =
            make_float2(tf32f(acc_o[nt][2] * inv1), tf32f(acc_o[nt][3] * inv1));
    }
}

// ---------------------------------------------------------------------------
// Launch pipeline (7 launches; ncu -s 5 captures attn_mma_kernel).
// Inputs: 0 H | 1 pos | 2 cos | 3 sin | 4 Wq | 5 Wk | 6 Wv | 7 Wo
// ---------------------------------------------------------------------------
extern "C" void kernel_launch(void* const* d_in, const int* in_sizes, int n_in,
                              void* d_out, int out_size)
{
    const float* H    = (const float*)d_in[0];
    const float* cosp = (const float*)d_in[2];
    const float* sinp = (const float*)d_in[3];
    const float* Wq   = (const float*)d_in[4];
    const float* Wk   = (const float*)d_in[5];
    const float* Wv   = (const float*)d_in[6];
    const float* Wo   = (const float*)d_in[7];
    float* out = (float*)d_out;

    float *qkv, *attn, *Hr, *Wr, *Wor;
    cudaGetSymbolAddress((void**)&qkv,  g_qkv);
    cudaGetSymbolAddress((void**)&attn, g_attn);
    cudaGetSymbolAddress((void**)&Hr,   g_Hr);
    cudaGetSymbolAddress((void**)&Wr,   g_Wr);
    cudaGetSymbolAddress((void**)&Wor,  g_Wor);

    cudaFuncSetAttribute(tf32gemm3, cudaFuncAttributeMaxDynamicSharedMemorySize, GEMM_SMEM_BYTES);
    cudaFuncSetAttribute(attn_mma_kernel, cudaFuncAttributeMaxDynamicSharedMemorySize, ATT_SMEM_BYTES);

    // Prep (3 launches)
    prep_round_HWo<<<1024, 256>>>((const float4*)H, (float4*)Hr,
                                  (const float4*)Wo, (float4*)Wor);
    prep_pack_Wq<<<1024, 256>>>((const float4*)Wq, (float4*)Wr);
    prep_pack_WkWv<<<1024, 256>>>((const float4*)Wk, (const float4*)Wv, (float4*)Wr);

    // Fused QKV projection (launch 4)
    tf32gemm3<<<dim3(QKV_N / 128, T_SEQ / 128), 256, GEMM_SMEM_BYTES>>>(
        Hr, Wr, qkv, T_SEQ, QKV_N, HID);

    // RoPE (launch 5)
    rope_round_kernel<<<T_SEQ, 256>>>(cosp, sinp);

    // Attention (launch 6 — ncu capture target)
    attn_mma_kernel<<<dim3(T_SEQ / 64, HQ), 128, ATT_SMEM_BYTES>>>();

    // Output projection (launch 7)
    tf32gemm3<<<dim3(HID / 128, T_SEQ / 128), 256, GEMM_SMEM_BYTES>>>(
        attn, Wor, out, T_SEQ, HID, HQ * DH);
}

// round 8
// speedup vs baseline: 1.2126x; 1.0295x over previous
#include <cuda_runtime.h>
#include <cuda_bf16.h>
#include <math.h>

#define T_SEQ 2048
#define HID   4096
#define HQ    32
#define HKV   8
#define DH    128
#define GROUPS (HQ / HKV)
#define QKV_N 6144                      // 4096 q | 1024 k | 1024 v
#define K_OFF 4096
#define V_OFF 5120

// q pre-scale: 1/sqrt(128) * log2(e)  (softmax runs in exp2 domain)
#define QSCALE_F ((float)(0.08838834764831845 * 1.4426950408889634))

// ---------------- device scratch (no allocs allowed) ----------------
__device__ float g_qkv[T_SEQ * QKV_N];      // 50 MB  fused q|k|v
__device__ float g_attn[T_SEQ * HQ * DH];   // 32 MB (tf32-rounded)
__device__ float g_Hr [T_SEQ * HID];        // 32 MB  tf32-rounded H
__device__ float g_Wr [HID * QKV_N];        // 100 MB tf32-rounded [Wq|Wk|Wv]
__device__ float g_Wor[HQ * DH * HID];      // 64 MB  tf32-rounded Wo

__device__ __forceinline__ unsigned tf32_cvt(float x) {
    unsigned r;
    asm("cvt.rna.tf32.f32 %0, %1;" : "=r"(r) : "f"(x));
    return r;
}
__device__ __forceinline__ float tf32f(float x) { return __uint_as_float(tf32_cvt(x)); }

__device__ __forceinline__ void mma_tf32(float* d, const unsigned* a, const unsigned* b) {
    asm volatile(
        "mma.sync.aligned.m16n8k8.row.col.f32.tf32.tf32.f32 "
        "{%0,%1,%2,%3}, {%4,%5,%6,%7}, {%8,%9}, {%0,%1,%2,%3};"
        : "+f"(d[0]), "+f"(d[1]), "+f"(d[2]), "+f"(d[3])
        : "r"(a[0]), "r"(a[1]), "r"(a[2]), "r"(a[3]), "r"(b[0]), "r"(b[1]));
}

// ldmatrix x4: lane L supplies row address; reg m of lane L = 4B at
// addr[matrix m, row L>>2] + (L&3)*4.  (32-bit elements ride on .b16 layout)
__device__ __forceinline__ void ldsm_x4(unsigned* r, unsigned a) {
    asm volatile("ldmatrix.sync.aligned.m8n8.x4.shared.b16 {%0,%1,%2,%3}, [%4];"
                 : "=r"(r[0]), "=r"(r[1]), "=r"(r[2]), "=r"(r[3]) : "r"(a));
}

__device__ __forceinline__ void cp_async16(void* smem_dst, const void* gmem_src) {
    unsigned s = (unsigned)__cvta_generic_to_shared(smem_dst);
    asm volatile("cp.async.cg.shared.global [%0], [%1], 16;" :: "r"(s), "l"(gmem_src));
}

// MUFU exp2 (force fast path)
__device__ __forceinline__ float ex2_mufu(float x) {
    float y;
    asm("ex2.approx.ftz.f32 %0, %1;" : "=f"(y) : "f"(x));
    return y;
}

// FMA-pipe exp2: minimax on f in [-0.5, 0.5], ~1e-7 rel err.
__device__ __forceinline__ float exp2_poly(float x) {
    x = fmaxf(x, -120.f);
    float t = x + 12582912.f;
    float i = t - 12582912.f;
    float f = x - i;
    float p = 1.535336188319500e-4f;
    p = fmaf(p, f, 1.339887440266574e-3f);
    p = fmaf(p, f, 9.618437357674640e-3f);
    p = fmaf(p, f, 5.550332471162809e-2f);
    p = fmaf(p, f, 2.402264791363012e-1f);
    p = fmaf(p, f, 6.931472028550421e-1f);
    p = fmaf(p, f, 1.0f);
    int ii = (int)i;
    return p * __int_as_float((ii + 127) << 23);
}

// ---------------------------------------------------------------------------
// Prep 1: round H and Wo to tf32 (two regions, one launch)
// ---------------------------------------------------------------------------
__global__ void prep_round_HWo(const float4* __restrict__ H, float4* __restrict__ Hr,
                               const float4* __restrict__ Wo, float4* __restrict__ Wor)
{
    const int nH = T_SEQ * HID / 4;
    const int nO = HQ * DH * HID / 4;
    int stride = gridDim.x * blockDim.x;
    for (int i = blockIdx.x * blockDim.x + threadIdx.x; i < nH + nO; i += stride) {
        const float4* s = (i < nH) ? H + i : Wo + (i - nH);
        float4* d       = (i < nH) ? Hr + i : Wor + (i - nH);
        float4 v = *s;
        v.x = tf32f(v.x); v.y = tf32f(v.y); v.z = tf32f(v.z); v.w = tf32f(v.w);
        *d = v;
    }
}

// Prep 2: pack Wq (rounded) into fused weight at col offset 0
__global__ void prep_pack_Wq(const float4* __restrict__ Wq, float4* __restrict__ Wr)
{
    const int n4 = HID * 4096 / 4;
    int stride = gridDim.x * blockDim.x;
    for (int i = blockIdx.x * blockDim.x + threadIdx.x; i < n4; i += stride) {
        int r = i >> 10, c = i & 1023;            // srcW4 = 1024
        float4 v = Wq[i];
        v.x = tf32f(v.x); v.y = tf32f(v.y); v.z = tf32f(v.z); v.w = tf32f(v.w);
        Wr[(size_t)r * (QKV_N / 4) + c] = v;
    }
}

// Prep 3: pack Wk (col 1024) and Wv (col 1280)
__global__ void prep_pack_WkWv(const float4* __restrict__ Wk,
                               const float4* __restrict__ Wv, float4* __restrict__ Wr)
{
    const int n4 = HID * 1024 / 4;                // per matrix
    int stride = gridDim.x * blockDim.x;
    for (int i = blockIdx.x * blockDim.x + threadIdx.x; i < 2 * n4; i += stride) {
        int which = (i >= n4);
        int j = which ? i - n4 : i;
        int r = j >> 8, c = j & 255;              // srcW4 = 256
        float4 v = which ? Wv[j] : Wk[j];
        v.x = tf32f(v.x); v.y = tf32f(v.y); v.z = tf32f(v.z); v.w = tf32f(v.w);
        Wr[(size_t)r * (QKV_N / 4) + (which ? 1280 : 1024) + c] = v;
    }
}

// ---------------------------------------------------------------------------
// TF32 tensor GEMM, 3-stage cp.async pipeline, ldmatrix A-fragments.
// C[M,N] = A[M,K] @ B[K,N]. Tile 128x128x32, 8 warps, warp 64x32.
// ---------------------------------------------------------------------------
#define GEMM_SMEM_BYTES (3 * (128 * 36 + 32 * 136) * 4)

__global__ __launch_bounds__(256, 2) void tf32gemm3(const float* __restrict__ A,
                                                    const float* __restrict__ B,
                                                    float* __restrict__ C,
                                                    int M, int N, int K)
{
    extern __shared__ float sm[];
    const int tid  = threadIdx.x;
    const int wid  = tid >> 5;
    const int lane = tid & 31;
    const int g    = lane >> 2;
    const int tg   = lane & 3;
    const int wm   = (wid >> 2) * 64;
    const int wn   = (wid & 3) * 32;
    const int bm   = blockIdx.y * 128;
    const int bn   = blockIdx.x * 128;

    const float* Ab = A + (size_t)bm * K;
    const float* Bb = B + bn;

    // ldmatrix lane offset within an A stage (bytes):
    // row (lane&15), col (lane>>4)*4 floats
    const unsigned a_lane_off = (((lane & 15) * 36 + (lane >> 4) * 4) << 2);

    float acc[4][4][4];
#pragma unroll
    for (int mt = 0; mt < 4; mt++)
#pragma unroll
        for (int nt = 0; nt < 4; nt++)
#pragma unroll
            for (int i = 0; i < 4; i++) acc[mt][nt][i] = 0.f;

    const int ntiles = K >> 5;

    auto issue = [&](int t) {
        float* As_ = sm + (t % 3) * 8960;
        float* Bs_ = As_ + 4608;
        const int kt = t << 5;
#pragma unroll
        for (int i_ = 0; i_ < 4; i_++) {
            int f4 = tid + i_ * 256;
            int r_ = f4 >> 3, c4_ = (f4 & 7) << 2;
            cp_async16(As_ + r_ * 36 + c4_, Ab + (size_t)r_ * K + kt + c4_);
            int rb_ = f4 >> 5, cb4_ = (f4 & 31) << 2;
            cp_async16(Bs_ + rb_ * 136 + cb4_, Bb + (size_t)(kt + rb_) * N + cb4_);
        }
        asm volatile("cp.async.commit_group;");
    };

    issue(0);
    issue(1);

    for (int t = 0; t < ntiles; t++) {
        if (t == ntiles - 1) asm volatile("cp.async.wait_group 0;");
        else                 asm volatile("cp.async.wait_group 1;");
        __syncthreads();
        if (t + 2 < ntiles) issue(t + 2);

        const float* As_ = sm + (t % 3) * 8960;
        const float* Bs_ = As_ + 4608;
        const unsigned a_base =
            (unsigned)__cvta_generic_to_shared(As_) + a_lane_off;

#pragma unroll
        for (int kk = 0; kk < 32; kk += 8) {
            unsigned af[4][4], bf[4][2];
#pragma unroll
            for (int mt = 0; mt < 4; mt++)
                ldsm_x4(af[mt], a_base + ((((wm + mt * 16) * 36) + kk) << 2));
#pragma unroll
            for (int nt = 0; nt < 4; nt++) {
                int col = wn + nt * 8;
                bf[nt][0] = __float_as_uint(Bs_[(kk + tg) * 136 + col + g]);
                bf[nt][1] = __float_as_uint(Bs_[(kk + tg + 4) * 136 + col + g]);
            }
#pragma unroll
            for (int mt = 0; mt < 4; mt++)
#pragma unroll
                for (int nt = 0; nt < 4; nt++)
                    mma_tf32(acc[mt][nt], af[mt], bf[nt]);
        }
    }

#pragma unroll
    for (int mt = 0; mt < 4; mt++) {
#pragma unroll
        for (int nt = 0; nt < 4; nt++) {
            int row = bm + wm + mt * 16 + g;
            int col = bn + wn + nt * 8 + tg * 2;
            *(float2*)&C[(size_t)row * N + col]       = make_float2(acc[mt][nt][0], acc[mt][nt][1]);
            *(float2*)&C[(size_t)(row + 8) * N + col] = make_float2(acc[mt][nt][2], acc[mt][nt][3]);
        }
    }
}

// ---------------------------------------------------------------------------
// RoPE in-place on fused qkv. Q pre-scaled by 1/sqrt(D)*log2(e). tf32 rounding.
// ---------------------------------------------------------------------------
__global__ void rope_round_kernel(const float* __restrict__ cosp,
                                  const float* __restrict__ sinp)
{
    const int t = blockIdx.x;
    float* rowp = &g_qkv[(size_t)t * QKV_N];
    for (int p = threadIdx.x; p < (HQ + HKV) * 64; p += blockDim.x) {
        int h = p >> 6;
        int d = p & 63;
        float c = cosp[t * DH + d];
        float s = sinp[t * DH + d];
        float* base = (h < HQ) ? rowp + h * DH : rowp + K_OFF + (h - HQ) * DH;
        float sc = (h < HQ) ? QSCALE_F : 1.0f;
        float x1 = base[d];
        float x2 = base[d + 64];
        base[d]      = tf32f((x1 * c - x2 * s) * sc);
        base[d + 64] = tf32f((x2 * c + x1 * s) * sc);
    }
    for (int i = threadIdx.x; i < HKV * DH; i += blockDim.x) {
        float* pv = rowp + V_OFF + i;
        *pv = tf32f(*pv);
    }
}

// ---------------------------------------------------------------------------
// Tensor-core flash attention (64 queries x 1 head, 128 threads, 2 CTAs/SM).
// No-max exp2 softmax; 25% poly / 75% MUFU exp split. (unchanged from R7)
// ---------------------------------------------------------------------------
#define ATT_SMEM_BYTES ((64 * 132 + 64 * 136 + 64 * 68) * 4)

__global__ __launch_bounds__(128, 2) void attn_mma_kernel()
{
    extern __shared__ float smf[];
    float* Ks = smf;                 // [64][132]
    float* Vs = smf + 64 * 132;      // [64][136]
    float* Ps = Vs + 64 * 136;       // [64][68]

    const int h    = blockIdx.y;
    const int kvh  = h / GROUPS;
    const int qi   = gridDim.x - 1 - blockIdx.x;   // long CTAs first
    const int q0   = qi * 64;
    const int tid  = threadIdx.x;
    const int w    = tid >> 5;
    const int lane = tid & 31;
    const int g    = lane >> 2;
    const int tg   = lane & 3;
    const int wrow = w * 16;

    for (int idx = tid; idx < 64 * 32; idx += 128) {
        int r = idx >> 5, c4 = (idx & 31) << 2;
        *(float4*)&Ks[r * 132 + c4] =
            *(const float4*)&g_qkv[(size_t)(q0 + r) * QKV_N + h * DH + c4];
    }
    __syncthreads();
    unsigned qf[16][4];
#pragma unroll
    for (int kk8 = 0; kk8 < 16; kk8++) {
        qf[kk8][0] = __float_as_uint(Ks[(wrow + g) * 132 + kk8 * 8 + tg]);
        qf[kk8][1] = __float_as_uint(Ks[(wrow + g + 8) * 132 + kk8 * 8 + tg]);
        qf[kk8][2] = __float_as_uint(Ks[(wrow + g) * 132 + kk8 * 8 + tg + 4]);
        qf[kk8][3] = __float_as_uint(Ks[(wrow + g + 8) * 132 + kk8 * 8 + tg + 4]);
    }
    __syncthreads();

    float acc_o[16][4];
#pragma unroll
    for (int nt = 0; nt < 16; nt++)
#pragma unroll
        for (int i = 0; i < 4; i++) acc_o[nt][i] = 0.f;
    float l0 = 0.f, l1 = 0.f;

    for (int k0 = 0; k0 <= q0; k0 += 64) {
        for (int idx = tid; idx < 64 * 32; idx += 128) {
            int r = idx >> 5, c4 = (idx & 31) << 2;
            size_t off = (size_t)(k0 + r) * QKV_N + kvh * DH + c4;
            *(float4*)&Ks[r * 132 + c4] = *(const float4*)&g_qkv[off + K_OFF];
            *(float4*)&Vs[r * 136 + c4] = *(const float4*)&g_qkv[off + V_OFF];
        }
        __syncthreads();

        float acc_s[8][4];
#pragma unroll
        for (int nt = 0; nt < 8; nt++)
#pragma unroll
            for (int i = 0; i < 4; i++) acc_s[nt][i] = 0.f;
#pragma unroll
        for (int kk8 = 0; kk8 < 16; kk8++) {
#pragma unroll
            for (int nt = 0; nt < 8; nt++) {
                unsigned b[2];
                b[0] = __float_as_uint(Ks[(nt * 8 + g) * 132 + kk8 * 8 + tg]);
                b[1] = __float_as_uint(Ks[(nt * 8 + g) * 132 + kk8 * 8 + tg + 4]);
                mma_tf32(acc_s[nt], qf[kk8], b);
            }
        }

        const bool diag = (k0 == q0);
        const int r0 = q0 + wrow + g, r1 = r0 + 8;
#pragma unroll
        for (int nt = 0; nt < 8; nt++) {
            float x0 = acc_s[nt][0] - 32.f;
            float x1 = acc_s[nt][1] - 32.f;
            float x2 = acc_s[nt][2] - 32.f;
            float x3 = acc_s[nt][3] - 32.f;
            if (diag) {
                int col0 = k0 + nt * 8 + tg * 2;
                if (col0     > r0) x0 = -1e30f;
                if (col0 + 1 > r0) x1 = -1e30f;
                if (col0     > r1) x2 = -1e30f;
                if (col0 + 1 > r1) x3 = -1e30f;
            }
            float p0, p1, p2, p3;
            if (nt < 2) {                      // 25% on FMA pipe
                p0 = exp2_poly(x0); p1 = exp2_poly(x1);
                p2 = exp2_poly(x2); p3 = exp2_poly(x3);
            } else {                           // 75% on MUFU
                p0 = ex2_mufu(x0); p1 = ex2_mufu(x1);
                p2 = ex2_mufu(x2); p3 = ex2_mufu(x3);
            }
            l0 += p0 + p1;
            l1 += p2 + p3;
            *(float2*)&Ps[(wrow + g) * 68 + nt * 8 + tg * 2]     = make_float2(tf32f(p0), tf32f(p1));
            *(float2*)&Ps[(wrow + g + 8) * 68 + nt * 8 + tg * 2] = make_float2(tf32f(p2), tf32f(p3));
        }
        __syncwarp();

#pragma unroll
        for (int kk8 = 0; kk8 < 8; kk8++) {
            unsigned a[4];
            a[0] = __float_as_uint(Ps[(wrow + g) * 68 + kk8 * 8 + tg]);
            a[1] = __float_as_uint(Ps[(wrow + g + 8) * 68 + kk8 * 8 + tg]);
            a[2] = __float_as_uint(Ps[(wrow + g) * 68 + kk8 * 8 + tg + 4]);
            a[3] = __float_as_uint(Ps[(wrow + g + 8) * 68 + kk8 * 8 + tg + 4]);
#pragma unroll
            for (int nt = 0; nt < 16; nt++) {
                unsigned b[2];
                b[0] = __float_as_uint(Vs[(kk8 * 8 + tg) * 136 + nt * 8 + g]);
                b[1] = __float_as_uint(Vs[(kk8 * 8 + tg + 4) * 136 + nt * 8 + g]);
                mma_tf32(acc_o[nt], a, b);
            }
        }
        __syncthreads();
    }

    l0 += __shfl_xor_sync(0xffffffffu, l0, 1);
    l0 += __shfl_xor_sync(0xffffffffu, l0, 2);
    l1 += __shfl_xor_sync(0xffffffffu, l1, 1);
    l1 += __shfl_xor_sync(0xffffffffu, l1, 2);
    const float inv0 = 1.f / l0;
    const float inv1 = 1.f / l1;

    const int row0 = q0 + wrow + g, row1 = row0 + 8;
#pragma unroll
    for (int nt = 0; nt < 16; nt++) {
        int col = h * DH + nt * 8 + tg * 2;
        *(float2*)&g_attn[(size_t)row0 * (HQ * DH) + col] =
            make_float2(tf32f(acc_o[nt][0] * inv0), tf32f(acc_o[nt][1] * inv0));
        *(float2*)&g_attn[(size_t)row1 * (HQ * DH) + col] =
            make_float2(tf32f(acc_o[nt][2] * inv1), tf32f(acc_o[nt][3] * inv1));
    }
}

// ---------------------------------------------------------------------------
// Launch pipeline (7 launches; ncu -s 5 captures attn_mma_kernel).
// Inputs: 0 H | 1 pos | 2 cos | 3 sin | 4 Wq | 5 Wk | 6 Wv | 7 Wo
// ---------------------------------------------------------------------------
extern "C" void kernel_launch(void* const* d_in, const int* in_sizes, int n_in,
                              void* d_out, int out_size)
{
    const float* H    = (const float*)d_in[0];
    const float* cosp = (const float*)d_in[2];
    const float* sinp = (const float*)d_in[3];
    const float* Wq   = (const float*)d_in[4];
    const float* Wk   = (const float*)d_in[5];
    const float* Wv   = (const float*)d_in[6];
    const float* Wo   = (const float*)d_in[7];
    float* out = (float*)d_out;

    float *qkv, *attn, *Hr, *Wr, *Wor;
    cudaGetSymbolAddress((void**)&qkv,  g_qkv);
    cudaGetSymbolAddress((void**)&attn, g_attn);
    cudaGetSymbolAddress((void**)&Hr,   g_Hr);
    cudaGetSymbolAddress((void**)&Wr,   g_Wr);
    cudaGetSymbolAddress((void**)&Wor,  g_Wor);

    cudaFuncSetAttribute(tf32gemm3, cudaFuncAttributeMaxDynamicSharedMemorySize, GEMM_SMEM_BYTES);
    cudaFuncSetAttribute(attn_mma_kernel, cudaFuncAttributeMaxDynamicSharedMemorySize, ATT_SMEM_BYTES);

    // Prep (3 launches)
    prep_round_HWo<<<1024, 256>>>((const float4*)H, (float4*)Hr,
                                  (const float4*)Wo, (float4*)Wor);
    prep_pack_Wq<<<1024, 256>>>((const float4*)Wq, (float4*)Wr);
    prep_pack_WkWv<<<1024, 256>>>((const float4*)Wk, (const float4*)Wv, (float4*)Wr);

    // Fused QKV projection (launch 4)
    tf32gemm3<<<dim3(QKV_N / 128, T_SEQ / 128), 256, GEMM_SMEM_BYTES>>>(
        Hr, Wr, qkv, T_SEQ, QKV_N, HID);

    // RoPE (launch 5)
    rope_round_kernel<<<T_SEQ, 256>>>(cosp, sinp);

    // Attention (launch 6 — ncu capture target)
    attn_mma_kernel<<<dim3(T_SEQ / 64, HQ), 128, ATT_SMEM_BYTES>>>();

    // Output projection (launch 7)
    tf32gemm3<<<dim3(HID / 128, T_SEQ / 128), 256, GEMM_SMEM_BYTES>>>(
        attn, Wor, out, T_SEQ, HID, HQ * DH);
}